// round 1
// baseline (speedup 1.0000x reference)
#include <cuda_runtime.h>
#include <cuda_bf16.h>

// Problem constants (fixed shapes: B=2, C=16, D=64, H=128, W=128)
#define NVOX   (64 * 128 * 128)          // 1,048,576 voxels per batch
#define NCLS   16
#define NB     2
#define QUADS_PER_BATCH (NVOX / 4)       // 262,144
#define BLOCKS_PER_BATCH 512
#define THREADS 256
#define ITERS  (QUADS_PER_BATCH / (BLOCKS_PER_BATCH * THREADS))  // 2

// Scratch (device globals — allocation in kernel_launch is forbidden)
__device__ float g_sum[NB * NCLS];
__device__ float g_cnt[NB * NCLS];
__device__ int   g_y_is_64;

// ---------------------------------------------------------------------------
// Kernel 1: zero the 32+32 accumulators and detect label dtype.
// If y is int64 (little-endian) every odd int32 word is exactly 0 (labels in
// [0,16)). If y is int32, odd words are real labels — P(all 32 sampled odd
// words == 0 | int32) = 16^-32 ~ 0.
// ---------------------------------------------------------------------------
__global__ void zero_detect_kernel(const int* __restrict__ y32) {
    int t = threadIdx.x;  // 32 threads
    g_sum[t] = 0.0f;
    g_cnt[t] = 0.0f;
    int v = y32[2 * t + 1];
    unsigned any_nonzero = __ballot_sync(0xffffffffu, v != 0);
    if (t == 0) g_y_is_64 = (any_nonzero == 0u) ? 1 : 0;
}

// ---------------------------------------------------------------------------
// Kernel 2: main pass. Per voxel: nll = log(sum_c exp(x_c)) - x_label,
// binned into per-thread register accumulators (16 sums + 16 counts),
// block-reduced via rotated shared atomics, then one global atomicAdd
// per (block, bin).
// ---------------------------------------------------------------------------
__global__ __launch_bounds__(THREADS)
void ce_main_kernel(const float* __restrict__ x, const void* __restrict__ y) {
    const int blk      = blockIdx.x;
    const int b        = blk / BLOCKS_PER_BATCH;          // batch index 0..1
    const int blk_in_b = blk - b * BLOCKS_PER_BATCH;
    const float* xb = x + (size_t)b * NCLS * NVOX;
    const bool y64 = (g_y_is_64 != 0);

    float fsum[NCLS];
    int   icnt[NCLS];
#pragma unroll
    for (int c = 0; c < NCLS; c++) { fsum[c] = 0.0f; icnt[c] = 0; }

    for (int it = 0; it < ITERS; it++) {
        const int q = (it * BLOCKS_PER_BATCH + blk_in_b) * THREADS + threadIdx.x;
        const int n = q * 4;  // first voxel of this quad

        int lab0, lab1, lab2, lab3;
        if (y64) {
            const longlong2* yp =
                (const longlong2*)((const long long*)y + (size_t)b * NVOX + n);
            longlong2 l0 = yp[0];
            longlong2 l1 = yp[1];
            lab0 = (int)l0.x; lab1 = (int)l0.y;
            lab2 = (int)l1.x; lab3 = (int)l1.y;
        } else {
            int4 l = *(const int4*)((const int*)y + (size_t)b * NVOX + n);
            lab0 = l.x; lab1 = l.y; lab2 = l.z; lab3 = l.w;
        }

        float s0 = 0.f, s1 = 0.f, s2 = 0.f, s3 = 0.f;
        float xl0 = 0.f, xl1 = 0.f, xl2 = 0.f, xl3 = 0.f;
#pragma unroll
        for (int c = 0; c < NCLS; c++) {
            float4 v = *(const float4*)(xb + (size_t)c * NVOX + n);
            s0 += __expf(v.x);
            s1 += __expf(v.y);
            s2 += __expf(v.z);
            s3 += __expf(v.w);
            if (lab0 == c) xl0 = v.x;
            if (lab1 == c) xl1 = v.y;
            if (lab2 == c) xl2 = v.z;
            if (lab3 == c) xl3 = v.w;
        }

        const float nll0 = __logf(s0) - xl0;
        const float nll1 = __logf(s1) - xl1;
        const float nll2 = __logf(s2) - xl2;
        const float nll3 = __logf(s3) - xl3;

#pragma unroll
        for (int c = 0; c < NCLS; c++) {
            if (lab0 == c) { fsum[c] += nll0; icnt[c]++; }
            if (lab1 == c) { fsum[c] += nll1; icnt[c]++; }
            if (lab2 == c) { fsum[c] += nll2; icnt[c]++; }
            if (lab3 == c) { fsum[c] += nll3; icnt[c]++; }
        }
    }

    // Block reduction: rotated shared atomics (conflict degree 2)
    __shared__ float s_sum[NCLS];
    __shared__ int   s_cnt[NCLS];
    if (threadIdx.x < NCLS) { s_sum[threadIdx.x] = 0.0f; s_cnt[threadIdx.x] = 0; }
    __syncthreads();

    const int rot = threadIdx.x & (NCLS - 1);
#pragma unroll
    for (int k = 0; k < NCLS; k++) {
        const int c = (rot + k) & (NCLS - 1);
        atomicAdd(&s_sum[c], fsum[c]);
        atomicAdd(&s_cnt[c], icnt[c]);
    }
    __syncthreads();

    if (threadIdx.x < NCLS) {
        atomicAdd(&g_sum[b * NCLS + threadIdx.x], s_sum[threadIdx.x]);
        atomicAdd(&g_cnt[b * NCLS + threadIdx.x], (float)s_cnt[threadIdx.x]);
    }
}

// ---------------------------------------------------------------------------
// Kernel 3: finalize. means where count>0, sum over all (b,c), / (B*C).
// result = mean_b [ (1/C) * sum_c mean_{label==c} nll ] = sum(means)/(B*C)
// ---------------------------------------------------------------------------
__global__ void ce_final_kernel(float* __restrict__ out) {
    const int t = threadIdx.x;  // 32 threads = 32 (b,c) bins
    const float s = g_sum[t];
    const float c = g_cnt[t];
    float m = (c > 0.0f) ? (s / c) : 0.0f;
#pragma unroll
    for (int o = 16; o > 0; o >>= 1)
        m += __shfl_xor_sync(0xffffffffu, m, o);
    if (t == 0) out[0] = m / (float)(NB * NCLS);
}

// ---------------------------------------------------------------------------
extern "C" void kernel_launch(void* const* d_in, const int* in_sizes, int n_in,
                              void* d_out, int out_size) {
    const float* x = (const float*)d_in[0];
    const void*  y = d_in[1];

    zero_detect_kernel<<<1, 32>>>((const int*)y);
    ce_main_kernel<<<NB * BLOCKS_PER_BATCH, THREADS>>>(x, y);
    ce_final_kernel<<<1, 32>>>((float*)d_out);
}

// round 2
// speedup vs baseline: 1.2121x; 1.2121x over previous
#include <cuda_runtime.h>
#include <cuda_bf16.h>

// Fixed shapes: B=2, C=16, D=64, H=128, W=128
#define NVOX   (64 * 128 * 128)          // 1,048,576 voxels per batch
#define NCLS   16
#define NB     2
#define THREADS 256
#define BLOCKS_PER_BATCH 512
#define NBLOCKS (NB * BLOCKS_PER_BATCH)  // 1024
#define ITERS  ((NVOX / 4) / (BLOCKS_PER_BATCH * THREADS))  // 2

// Device-global scratch (zero-initialized at module load; the LAST block of
// every launch resets them to zero again, so each call sees zeros).
__device__ float    g_sum[NB * NCLS];
__device__ float    g_cnt[NB * NCLS];
__device__ unsigned g_ticket;

__global__ __launch_bounds__(THREADS)
void ce_fused_kernel(const float* __restrict__ x, const void* __restrict__ y,
                     float* __restrict__ out) {
    __shared__ float s_sum[NCLS];
    __shared__ int   s_cnt[NCLS];
    __shared__ int   sh_y64;
    __shared__ int   sh_last;

    const int tid      = threadIdx.x;
    const int blk      = blockIdx.x;
    const int b        = blk >> 9;            // / BLOCKS_PER_BATCH
    const int blk_in_b = blk & (BLOCKS_PER_BATCH - 1);
    const float* xb = x + (size_t)b * NCLS * NVOX;

    // Init shared bins + detect label dtype. If y is int64 (LE), every odd
    // int32 word is 0 (labels < 16). P(32 odd words all zero | int32) = 16^-32.
    if (tid < NCLS) { s_sum[tid] = 0.0f; s_cnt[tid] = 0; }
    if (tid < 32) {
        int v = ((const int*)y)[2 * tid + 1];
        unsigned nz = __ballot_sync(0xffffffffu, v != 0);
        if (tid == 0) sh_y64 = (nz == 0u) ? 1 : 0;
    }
    __syncthreads();
    const bool y64 = (sh_y64 != 0);

    // Per-thread accumulators: 16 float sums + 16 counters packed 4-per-reg
    // (max count per thread = ITERS*4 = 8, fits a byte).
    float    fsum[NCLS];
    unsigned cpak[4] = {0u, 0u, 0u, 0u};
#pragma unroll
    for (int c = 0; c < NCLS; c++) fsum[c] = 0.0f;

    for (int it = 0; it < ITERS; it++) {
        const int n = (((it * BLOCKS_PER_BATCH + blk_in_b) * THREADS) + tid) * 4;

        int lab0, lab1, lab2, lab3;
        if (y64) {
            const longlong2* yp =
                (const longlong2*)((const long long*)y + (size_t)b * NVOX + n);
            longlong2 l0 = yp[0];
            longlong2 l1 = yp[1];
            lab0 = (int)l0.x; lab1 = (int)l0.y;
            lab2 = (int)l1.x; lab3 = (int)l1.y;
        } else {
            int4 l = *(const int4*)((const int*)y + (size_t)b * NVOX + n);
            lab0 = l.x; lab1 = l.y; lab2 = l.z; lab3 = l.w;
        }

        float s0 = 0.f, s1 = 0.f, s2 = 0.f, s3 = 0.f;
        float xl0 = 0.f, xl1 = 0.f, xl2 = 0.f, xl3 = 0.f;
        // Cap unroll at 8 to limit load staging to 8 x float4 = 32 regs
        // (MLP 8 per thread is far above what's needed to fill HBM).
#pragma unroll 8
        for (int c = 0; c < NCLS; c++) {
            float4 v = *(const float4*)(xb + (size_t)c * NVOX + n);
            s0 += __expf(v.x);
            s1 += __expf(v.y);
            s2 += __expf(v.z);
            s3 += __expf(v.w);
            if (lab0 == c) xl0 = v.x;
            if (lab1 == c) xl1 = v.y;
            if (lab2 == c) xl2 = v.z;
            if (lab3 == c) xl3 = v.w;
        }

        const float nll0 = __logf(s0) - xl0;
        const float nll1 = __logf(s1) - xl1;
        const float nll2 = __logf(s2) - xl2;
        const float nll3 = __logf(s3) - xl3;

#pragma unroll
        for (int c = 0; c < NCLS; c++) {
            const unsigned inc = 1u << ((c & 3) * 8);
            if (lab0 == c) { fsum[c] += nll0; cpak[c >> 2] += inc; }
            if (lab1 == c) { fsum[c] += nll1; cpak[c >> 2] += inc; }
            if (lab2 == c) { fsum[c] += nll2; cpak[c >> 2] += inc; }
            if (lab3 == c) { fsum[c] += nll3; cpak[c >> 2] += inc; }
        }
    }

    // Block reduction: rotated shared atomics (16 bins, conflict degree ~2).
    const int rot = tid & (NCLS - 1);
#pragma unroll
    for (int k = 0; k < NCLS; k++) {
        const int c = (rot + k) & (NCLS - 1);
        atomicAdd(&s_sum[c], fsum[c]);
        atomicAdd(&s_cnt[c], (int)((cpak[c >> 2] >> ((c & 3) * 8)) & 0xffu));
    }
    __syncthreads();

    if (tid < NCLS) {
        atomicAdd(&g_sum[b * NCLS + tid], s_sum[tid]);
        atomicAdd(&g_cnt[b * NCLS + tid], (float)s_cnt[tid]);
    }

    // Last-block finalize (release: fence + ticket; acquire: fence after read).
    __threadfence();
    if (tid == 0) {
        unsigned t = atomicAdd(&g_ticket, 1u);
        sh_last = (t == (unsigned)(NBLOCKS - 1)) ? 1 : 0;
    }
    __syncthreads();

    if (sh_last) {
        __threadfence();
        if (tid < NB * NCLS) {
            // atomic reads bypass any stale L1 state
            const float s = atomicAdd(&g_sum[tid], 0.0f);
            const float c = atomicAdd(&g_cnt[tid], 0.0f);
            float m = (c > 0.0f) ? (s / c) : 0.0f;
#pragma unroll
            for (int o = 16; o > 0; o >>= 1)
                m += __shfl_xor_sync(0xffffffffu, m, o);
            if (tid == 0) {
                out[0] = m / (float)(NB * NCLS);
                g_ticket = 0u;               // restore state for next call
            }
            g_sum[tid] = 0.0f;
            g_cnt[tid] = 0.0f;
        }
    }
}

extern "C" void kernel_launch(void* const* d_in, const int* in_sizes, int n_in,
                              void* d_out, int out_size) {
    const float* x = (const float*)d_in[0];
    const void*  y = d_in[1];
    ce_fused_kernel<<<NBLOCKS, THREADS>>>(x, y, (float*)d_out);
}

// round 3
// speedup vs baseline: 1.4146x; 1.1670x over previous
#include <cuda_runtime.h>
#include <cuda_bf16.h>

// Fixed shapes: B=2, C=16, D=64, H=128, W=128
#define NVOX   (64 * 128 * 128)          // 1,048,576 voxels per batch
#define NCLS   16
#define NB     2
#define THREADS 256
#define BLOCKS_PER_BATCH 444
#define NBLOCKS (NB * BLOCKS_PER_BATCH)      // 888 = 148 SMs x 6 blocks
#define QPB    (NVOX / 4)                    // 262,144 quads per batch
#define QPI    (BLOCKS_PER_BATCH * THREADS)  // 113,664 quads per iteration
// iter 0,1 full; iter 2: 34,816 quads = exactly 136 blocks (uniform guard)

// Device-global scratch (zero-initialized at load; last block re-zeros after
// finalizing, so every launch sees zeros).
__device__ float    g_sum[NB * NCLS];
__device__ float    g_cnt[NB * NCLS];
__device__ unsigned g_ticket;

__global__ __launch_bounds__(THREADS, 6)
void ce_fused_kernel(const float* __restrict__ x, const void* __restrict__ y,
                     float* __restrict__ out) {
    // Per-thread private bins in shared memory, conflict-free layout:
    // address word = lab*256 + tid  ->  bank = tid % 32 (unique per lane).
    __shared__ float s_nll[NCLS][THREADS];
    __shared__ int   s_c[NCLS][THREADS];
    __shared__ int   sh_y64;
    __shared__ int   sh_last;

    const int tid      = threadIdx.x;
    const int blk      = blockIdx.x;
    const int b        = (blk >= BLOCKS_PER_BATCH) ? 1 : 0;
    const int blk_in_b = blk - b * BLOCKS_PER_BATCH;
    const float* xb = x + (size_t)b * NCLS * NVOX;

    // Zero private bins
#pragma unroll
    for (int c = 0; c < NCLS; c++) { s_nll[c][tid] = 0.0f; s_c[c][tid] = 0; }

    // Label dtype detect: int64 (LE) => every odd int32 word is 0 (labels<16).
    if (tid < 32) {
        int v = ((const int*)y)[2 * tid + 1];
        unsigned nz = __ballot_sync(0xffffffffu, v != 0);
        if (tid == 0) sh_y64 = (nz == 0u) ? 1 : 0;
    }
    __syncthreads();
    const bool y64 = (sh_y64 != 0);

#pragma unroll
    for (int it = 0; it < 3; it++) {
        const int q = it * QPI + blk_in_b * THREADS + tid;
        if (it == 2 && blk_in_b >= 136) break;   // uniform per block
        const int n = q * 4;

        int lab0, lab1, lab2, lab3;
        if (y64) {
            const longlong2* yp =
                (const longlong2*)((const long long*)y + (size_t)b * NVOX + n);
            longlong2 l0 = yp[0];
            longlong2 l1 = yp[1];
            lab0 = (int)l0.x; lab1 = (int)l0.y;
            lab2 = (int)l1.x; lab3 = (int)l1.y;
        } else {
            int4 l = *(const int4*)((const int*)y + (size_t)b * NVOX + n);
            lab0 = l.x; lab1 = l.y; lab2 = l.z; lab3 = l.w;
        }

        float s0 = 0.f, s1 = 0.f, s2 = 0.f, s3 = 0.f;
        float xl0 = 0.f, xl1 = 0.f, xl2 = 0.f, xl3 = 0.f;
#pragma unroll
        for (int c = 0; c < NCLS; c++) {
            float4 v = *(const float4*)(xb + (size_t)c * NVOX + n);
            s0 += __expf(v.x);
            s1 += __expf(v.y);
            s2 += __expf(v.z);
            s3 += __expf(v.w);
            if (lab0 == c) xl0 = v.x;
            if (lab1 == c) xl1 = v.y;
            if (lab2 == c) xl2 = v.z;
            if (lab3 == c) xl3 = v.w;
        }

        const float nll0 = __logf(s0) - xl0;
        const float nll1 = __logf(s1) - xl1;
        const float nll2 = __logf(s2) - xl2;
        const float nll3 = __logf(s3) - xl3;

        // Private shared bins: conflict-free RMW (bank = tid%32)
        s_nll[lab0][tid] += nll0;  s_c[lab0][tid]++;
        s_nll[lab1][tid] += nll1;  s_c[lab1][tid]++;
        s_nll[lab2][tid] += nll2;  s_c[lab2][tid]++;
        s_nll[lab3][tid] += nll3;  s_c[lab3][tid]++;
    }
    __syncthreads();

    // Block reduce: warp w handles labs {w, w+8}; lane sums 8 strided entries.
    const int w = tid >> 5, l = tid & 31;
#pragma unroll
    for (int lab = w; lab < NCLS; lab += 8) {
        float fs = 0.0f;
        int   ic = 0;
#pragma unroll
        for (int k = 0; k < 8; k++) {
            fs += s_nll[lab][l + 32 * k];
            ic += s_c[lab][l + 32 * k];
        }
#pragma unroll
        for (int o = 16; o > 0; o >>= 1) {
            fs += __shfl_xor_sync(0xffffffffu, fs, o);
            ic += __shfl_xor_sync(0xffffffffu, ic, o);
        }
        if (l == 0) {
            atomicAdd(&g_sum[b * NCLS + lab], fs);
            atomicAdd(&g_cnt[b * NCLS + lab], (float)ic);
        }
    }

    // Last-block finalize
    __threadfence();
    if (tid == 0) {
        unsigned t = atomicAdd(&g_ticket, 1u);
        sh_last = (t == (unsigned)(NBLOCKS - 1)) ? 1 : 0;
    }
    __syncthreads();

    if (sh_last) {
        __threadfence();
        if (tid < NB * NCLS) {
            const float s = atomicAdd(&g_sum[tid], 0.0f);
            const float c = atomicAdd(&g_cnt[tid], 0.0f);
            float m = (c > 0.0f) ? (s / c) : 0.0f;
#pragma unroll
            for (int o = 16; o > 0; o >>= 1)
                m += __shfl_xor_sync(0xffffffffu, m, o);
            if (tid == 0) {
                out[0] = m / (float)(NB * NCLS);
                g_ticket = 0u;
            }
            g_sum[tid] = 0.0f;
            g_cnt[tid] = 0.0f;
        }
    }
}

extern "C" void kernel_launch(void* const* d_in, const int* in_sizes, int n_in,
                              void* d_out, int out_size) {
    const float* x = (const float*)d_in[0];
    const void*  y = d_in[1];
    ce_fused_kernel<<<NBLOCKS, THREADS>>>(x, y, (float*)d_out);
}